// round 1
// baseline (speedup 1.0000x reference)
#include <cuda_runtime.h>
#include <cstdint>

// ---------------- problem constants ----------------
#define BATCH      4
#define N1_PER     16384
#define N2_PER     4096
#define N1_TOT     (BATCH * N1_PER)    // 65536
#define N2_TOT     (BATCH * N2_PER)    // 16384
#define C_IN       512
#define C_OUT      256
#define BN_EPS     1e-5f

// ---------------- device scratch (static, allocation-free) ----------------
__device__ float g_h2[N2_TOT * C_OUT];       // 16 MB: relu(bn(x2@W2^T))
__device__ float g_W1f[C_OUT * C_OUT];       // BN-folded weights
__device__ float g_W2f[C_OUT * C_IN];
__device__ float g_c1[C_OUT];                // BN-folded bias
__device__ float g_c2[C_OUT];

// ---------------- BN fold: Wf[n,k] = W[n,k]*s_n ; c[n] = (b-m)*s + beta ----
template <int WHICH>
__global__ void fold_kernel(const float* __restrict__ W, const float* __restrict__ b,
                            const float* __restrict__ g, const float* __restrict__ be,
                            const float* __restrict__ m, const float* __restrict__ v)
{
    const int Kd = (WHICH == 0) ? C_OUT : C_IN;
    float* Wf = (WHICH == 0) ? g_W1f : g_W2f;
    float* cf = (WHICH == 0) ? g_c1 : g_c2;
    int n = blockIdx.x;
    float s = g[n] / sqrtf(v[n] + BN_EPS);
    if (threadIdx.x == 0) cf[n] = (b[n] - m[n]) * s + be[n];
    for (int k = threadIdx.x; k < Kd; k += blockDim.x)
        Wf[n * Kd + k] = W[n * Kd + k] * s;
}

// ---------------- fused GEMM + bias + ReLU -----------------
// C[m,n] = relu( sum_k A[m,k]*Wf[n,k] + c[n] ),  N fixed = 256
// 128x128 tile, BK=8, 256 threads, 8x8 microtile.
template <int WHICH>
__global__ __launch_bounds__(256, 2) void gemm_bias_relu(
    const float* __restrict__ A, float* __restrict__ C, int M, int K)
{
    const float* __restrict__ Bw  = (WHICH == 0) ? g_W1f : g_W2f;
    const float* __restrict__ cb  = (WHICH == 0) ? g_c1  : g_c2;

    __shared__ float As[8][128];
    __shared__ float Bs[8][128];

    const int tid = threadIdx.x;
    const int tx  = tid & 15;        // 0..15 -> n microtile
    const int ty  = tid >> 4;        // 0..15 -> m microtile
    const int bn  = blockIdx.x * 128;
    const int bm  = blockIdx.y * 128;

    const int lr = tid >> 1;         // 0..127 row within tile
    const int lc = (tid & 1) * 4;    // 0 or 4 (k offset)

    const float* Ap = A  + (size_t)(bm + lr) * K + lc;
    const float* Bp = Bw + (size_t)(bn + lr) * K + lc;

    float acc[8][8];
#pragma unroll
    for (int i = 0; i < 8; i++)
#pragma unroll
        for (int j = 0; j < 8; j++) acc[i][j] = 0.f;

    for (int k0 = 0; k0 < K; k0 += 8) {
        float4 a = *(const float4*)(Ap + k0);
        float4 b = *(const float4*)(Bp + k0);
        As[lc + 0][lr] = a.x; As[lc + 1][lr] = a.y;
        As[lc + 2][lr] = a.z; As[lc + 3][lr] = a.w;
        Bs[lc + 0][lr] = b.x; Bs[lc + 1][lr] = b.y;
        Bs[lc + 2][lr] = b.z; Bs[lc + 3][lr] = b.w;
        __syncthreads();

#pragma unroll
        for (int kk = 0; kk < 8; kk++) {
            const float4* arow = (const float4*)&As[kk][ty * 8];
            const float4* brow = (const float4*)&Bs[kk][tx * 8];
            float4 a0 = arow[0], a1 = arow[1];
            float4 b0 = brow[0], b1 = brow[1];
            float ra[8] = {a0.x, a0.y, a0.z, a0.w, a1.x, a1.y, a1.z, a1.w};
            float rb[8] = {b0.x, b0.y, b0.z, b0.w, b1.x, b1.y, b1.z, b1.w};
#pragma unroll
            for (int i = 0; i < 8; i++)
#pragma unroll
                for (int j = 0; j < 8; j++)
                    acc[i][j] = fmaf(ra[i], rb[j], acc[i][j]);
        }
        __syncthreads();
    }

    float4 bv0 = *(const float4*)(cb + bn + tx * 8);
    float4 bv1 = *(const float4*)(cb + bn + tx * 8 + 4);
#pragma unroll
    for (int i = 0; i < 8; i++) {
        size_t m = (size_t)(bm + ty * 8 + i);
        float4 o0, o1;
        o0.x = fmaxf(acc[i][0] + bv0.x, 0.f);
        o0.y = fmaxf(acc[i][1] + bv0.y, 0.f);
        o0.z = fmaxf(acc[i][2] + bv0.z, 0.f);
        o0.w = fmaxf(acc[i][3] + bv0.w, 0.f);
        o1.x = fmaxf(acc[i][4] + bv1.x, 0.f);
        o1.y = fmaxf(acc[i][5] + bv1.y, 0.f);
        o1.z = fmaxf(acc[i][6] + bv1.z, 0.f);
        o1.w = fmaxf(acc[i][7] + bv1.w, 0.f);
        *(float4*)(C + m * 256 + bn + tx * 8)     = o0;
        *(float4*)(C + m * 256 + bn + tx * 8 + 4) = o1;
    }
}

// ---------------- kNN(k=3) + inverse-distance interp + add into out -------
// grid: (N1_PER/256, BATCH); block 256 threads; 64KB dyn smem (float4 pts).
__global__ __launch_bounds__(256) void knn_interp_kernel(
    const float* __restrict__ p1, const float* __restrict__ p2,
    float* __restrict__ out)
{
    extern __shared__ float4 pts[];   // [4096]

    const int scene = blockIdx.y;
    const int tid   = threadIdx.x;

    const float* p2s = p2 + (size_t)scene * N2_PER * 3;
    for (int i = tid; i < N2_PER; i += 256) {
        pts[i] = make_float4(p2s[3 * i + 0], p2s[3 * i + 1], p2s[3 * i + 2], 0.f);
    }
    __syncthreads();

    const int q = scene * N1_PER + blockIdx.x * 256 + tid;
    const float qx = p1[3 * q + 0];
    const float qy = p1[3 * q + 1];
    const float qz = p1[3 * q + 2];

    float b0 = 3.4e38f, b1 = 3.4e38f, b2 = 3.4e38f;
    int   i0 = 0, i1 = 0, i2 = 0;

#pragma unroll 8
    for (int k = 0; k < N2_PER; k++) {
        float4 p = pts[k];
        float dx = qx - p.x, dy = qy - p.y, dz = qz - p.z;
        float d  = fmaf(dx, dx, fmaf(dy, dy, dz * dz));
        if (d < b2) {
            if (d < b1) {
                b2 = b1; i2 = i1;
                if (d < b0) { b1 = b0; i1 = i0; b0 = d; i0 = k; }
                else        { b1 = d;  i1 = k; }
            } else { b2 = d; i2 = k; }
        }
    }

    // weights exactly as reference: 1/(sqrt(max(d2,1e-12))+1e-8), normalized
    float w0 = 1.f / (sqrtf(fmaxf(b0, 1e-12f)) + 1e-8f);
    float w1 = 1.f / (sqrtf(fmaxf(b1, 1e-12f)) + 1e-8f);
    float w2 = 1.f / (sqrtf(fmaxf(b2, 1e-12f)) + 1e-8f);
    float ws = w0 + w1 + w2;
    w0 = w0 / ws; w1 = w1 / ws; w2 = w2 / ws;

    // warp-cooperative gather: lane s's query served by the whole warp
    const unsigned full = 0xffffffffu;
    const int warp = tid >> 5, lane = tid & 31;
    const int h2base = scene * N2_PER;
    const int qbase  = scene * N1_PER + blockIdx.x * 256 + warp * 32;

    for (int s = 0; s < 32; s++) {
        float ww0 = __shfl_sync(full, w0, s);
        float ww1 = __shfl_sync(full, w1, s);
        float ww2 = __shfl_sync(full, w2, s);
        int   j0  = __shfl_sync(full, i0, s);
        int   j1  = __shfl_sync(full, i1, s);
        int   j2  = __shfl_sync(full, i2, s);
        const float4* r0 = (const float4*)(g_h2 + (size_t)(h2base + j0) * 256);
        const float4* r1 = (const float4*)(g_h2 + (size_t)(h2base + j1) * 256);
        const float4* r2 = (const float4*)(g_h2 + (size_t)(h2base + j2) * 256);
        float4* o = (float4*)(out + (size_t)(qbase + s) * 256);
#pragma unroll
        for (int c = 0; c < 2; c++) {
            int ci = lane + c * 32;         // 0..63 float4 slots (256 floats)
            float4 a = r0[ci], b = r1[ci], cc = r2[ci], ov = o[ci];
            ov.x += ww0 * a.x + ww1 * b.x + ww2 * cc.x;
            ov.y += ww0 * a.y + ww1 * b.y + ww2 * cc.y;
            ov.z += ww0 * a.z + ww1 * b.z + ww2 * cc.z;
            ov.w += ww0 * a.w + ww1 * b.w + ww2 * cc.w;
            o[ci] = ov;
        }
    }
}

// ---------------- launch -----------------
extern "C" void kernel_launch(void* const* d_in, const int* in_sizes, int n_in,
                              void* d_out, int out_size)
{
    const float* p1  = (const float*)d_in[0];
    const float* x1  = (const float*)d_in[1];
    const float* p2  = (const float*)d_in[2];
    const float* x2  = (const float*)d_in[3];
    const float* W1  = (const float*)d_in[4];
    const float* b1  = (const float*)d_in[5];
    const float* g1  = (const float*)d_in[6];
    const float* be1 = (const float*)d_in[7];
    const float* m1  = (const float*)d_in[8];
    const float* v1  = (const float*)d_in[9];
    const float* W2  = (const float*)d_in[10];
    const float* b2  = (const float*)d_in[11];
    const float* g2  = (const float*)d_in[12];
    const float* be2 = (const float*)d_in[13];
    const float* m2  = (const float*)d_in[14];
    const float* v2  = (const float*)d_in[15];
    float* out = (float*)d_out;

    // fold BN into weights/bias
    fold_kernel<0><<<C_OUT, 128>>>(W1, b1, g1, be1, m1, v1);
    fold_kernel<1><<<C_OUT, 128>>>(W2, b2, g2, be2, m2, v2);

    // h1 = relu(bn(x1@W1^T)) -> out directly
    {
        float* h2_dev = nullptr;  // gemm<1> writes to g_h2 internally via pointer arg
        (void)h2_dev;
        dim3 grid1(2, N1_TOT / 128);
        gemm_bias_relu<0><<<grid1, 256>>>(x1, out, N1_TOT, C_OUT);
    }
    // h2 = relu(bn(x2@W2^T)) -> g_h2
    {
        float* h2ptr = nullptr;
        cudaGetSymbolAddress((void**)&h2ptr, g_h2);
        dim3 grid2(2, N2_TOT / 128);
        gemm_bias_relu<1><<<grid2, 256>>>(x2, h2ptr, N2_TOT, C_IN);
    }

    // kNN interpolation, accumulate into out
    static bool attr_set = false;
    if (!attr_set) {
        cudaFuncSetAttribute(knn_interp_kernel,
                             cudaFuncAttributeMaxDynamicSharedMemorySize,
                             N2_PER * sizeof(float4));
        attr_set = true;
    }
    dim3 gridk(N1_PER / 256, BATCH);
    knn_interp_kernel<<<gridk, 256, N2_PER * sizeof(float4)>>>(p1, p2, out);
}

// round 2
// speedup vs baseline: 1.0472x; 1.0472x over previous
#include <cuda_runtime.h>
#include <cstdint>

// ---------------- problem constants ----------------
#define BATCH      4
#define N1_PER     16384
#define N2_PER     4096
#define N1_TOT     (BATCH * N1_PER)    // 65536
#define N2_TOT     (BATCH * N2_PER)    // 16384
#define C_IN       512
#define C_OUT      256
#define BN_EPS     1e-5f

// ---------------- device scratch (static, allocation-free) ----------------
__device__ float g_h2[N2_TOT * C_OUT];       // 16 MB: relu(bn(x2@W2^T))
__device__ float g_W1f[C_OUT * C_OUT];       // BN-folded weights
__device__ float g_W2f[C_OUT * C_IN];
__device__ float g_c1[C_OUT];                // BN-folded bias
__device__ float g_c2[C_OUT];

// ---------------- BN fold: Wf[n,k] = W[n,k]*s_n ; c[n] = (b-m)*s + beta ----
template <int WHICH>
__global__ void fold_kernel(const float* __restrict__ W, const float* __restrict__ b,
                            const float* __restrict__ g, const float* __restrict__ be,
                            const float* __restrict__ m, const float* __restrict__ v)
{
    const int Kd = (WHICH == 0) ? C_OUT : C_IN;
    float* Wf = (WHICH == 0) ? g_W1f : g_W2f;
    float* cf = (WHICH == 0) ? g_c1 : g_c2;
    int n = blockIdx.x;
    float s = g[n] / sqrtf(v[n] + BN_EPS);
    if (threadIdx.x == 0) cf[n] = (b[n] - m[n]) * s + be[n];
    for (int k = threadIdx.x; k < Kd; k += blockDim.x)
        Wf[n * Kd + k] = W[n * Kd + k] * s;
}

// ---------------- fused GEMM + bias + ReLU -----------------
// C[m,n] = relu( sum_k A[m,k]*Wf[n,k] + c[n] ),  N fixed = 256
// 128x128 tile, BK=8, 256 threads, 8x8 microtile.
template <int WHICH>
__global__ __launch_bounds__(256, 2) void gemm_bias_relu(
    const float* __restrict__ A, float* __restrict__ C, int M, int K)
{
    const float* __restrict__ Bw  = (WHICH == 0) ? g_W1f : g_W2f;
    const float* __restrict__ cb  = (WHICH == 0) ? g_c1  : g_c2;

    __shared__ float As[8][128];
    __shared__ float Bs[8][128];

    const int tid = threadIdx.x;
    const int tx  = tid & 15;        // 0..15 -> n microtile
    const int ty  = tid >> 4;        // 0..15 -> m microtile
    const int bn  = blockIdx.x * 128;
    const int bm  = blockIdx.y * 128;

    const int lr = tid >> 1;         // 0..127 row within tile
    const int lc = (tid & 1) * 4;    // 0 or 4 (k offset)

    const float* Ap = A  + (size_t)(bm + lr) * K + lc;
    const float* Bp = Bw + (size_t)(bn + lr) * K + lc;

    float acc[8][8];
#pragma unroll
    for (int i = 0; i < 8; i++)
#pragma unroll
        for (int j = 0; j < 8; j++) acc[i][j] = 0.f;

    for (int k0 = 0; k0 < K; k0 += 8) {
        float4 a = *(const float4*)(Ap + k0);
        float4 b = *(const float4*)(Bp + k0);
        As[lc + 0][lr] = a.x; As[lc + 1][lr] = a.y;
        As[lc + 2][lr] = a.z; As[lc + 3][lr] = a.w;
        Bs[lc + 0][lr] = b.x; Bs[lc + 1][lr] = b.y;
        Bs[lc + 2][lr] = b.z; Bs[lc + 3][lr] = b.w;
        __syncthreads();

#pragma unroll
        for (int kk = 0; kk < 8; kk++) {
            const float4* arow = (const float4*)&As[kk][ty * 8];
            const float4* brow = (const float4*)&Bs[kk][tx * 8];
            float4 a0 = arow[0], a1 = arow[1];
            float4 b0 = brow[0], b1 = brow[1];
            float ra[8] = {a0.x, a0.y, a0.z, a0.w, a1.x, a1.y, a1.z, a1.w};
            float rb[8] = {b0.x, b0.y, b0.z, b0.w, b1.x, b1.y, b1.z, b1.w};
#pragma unroll
            for (int i = 0; i < 8; i++)
#pragma unroll
                for (int j = 0; j < 8; j++)
                    acc[i][j] = fmaf(ra[i], rb[j], acc[i][j]);
        }
        __syncthreads();
    }

    float4 bv0 = *(const float4*)(cb + bn + tx * 8);
    float4 bv1 = *(const float4*)(cb + bn + tx * 8 + 4);
#pragma unroll
    for (int i = 0; i < 8; i++) {
        size_t m = (size_t)(bm + ty * 8 + i);
        float4 o0, o1;
        o0.x = fmaxf(acc[i][0] + bv0.x, 0.f);
        o0.y = fmaxf(acc[i][1] + bv0.y, 0.f);
        o0.z = fmaxf(acc[i][2] + bv0.z, 0.f);
        o0.w = fmaxf(acc[i][3] + bv0.w, 0.f);
        o1.x = fmaxf(acc[i][4] + bv1.x, 0.f);
        o1.y = fmaxf(acc[i][5] + bv1.y, 0.f);
        o1.z = fmaxf(acc[i][6] + bv1.z, 0.f);
        o1.w = fmaxf(acc[i][7] + bv1.w, 0.f);
        *(float4*)(C + m * 256 + bn + tx * 8)     = o0;
        *(float4*)(C + m * 256 + bn + tx * 8 + 4) = o1;
    }
}

// ---------------- kNN(k=3) + inverse-distance interp + add into out -------
// grid: (N1_PER/256, BATCH); block 256 threads; 64KB dyn smem (float4 pts).
__global__ __launch_bounds__(256) void knn_interp_kernel(
    const float* __restrict__ p1, const float* __restrict__ p2,
    float* __restrict__ out)
{
    extern __shared__ float4 pts[];   // [4096]

    const int scene = blockIdx.y;
    const int tid   = threadIdx.x;

    const float* p2s = p2 + (size_t)scene * N2_PER * 3;
    for (int i = tid; i < N2_PER; i += 256) {
        pts[i] = make_float4(p2s[3 * i + 0], p2s[3 * i + 1], p2s[3 * i + 2], 0.f);
    }
    __syncthreads();

    const int q = scene * N1_PER + blockIdx.x * 256 + tid;
    const float qx = p1[3 * q + 0];
    const float qy = p1[3 * q + 1];
    const float qz = p1[3 * q + 2];

    float b0 = 3.4e38f, b1 = 3.4e38f, b2 = 3.4e38f;
    int   i0 = 0, i1 = 0, i2 = 0;

#pragma unroll 8
    for (int k = 0; k < N2_PER; k++) {
        float4 p = pts[k];
        float dx = qx - p.x, dy = qy - p.y, dz = qz - p.z;
        float d  = fmaf(dx, dx, fmaf(dy, dy, dz * dz));
        if (d < b2) {
            if (d < b1) {
                b2 = b1; i2 = i1;
                if (d < b0) { b1 = b0; i1 = i0; b0 = d; i0 = k; }
                else        { b1 = d;  i1 = k; }
            } else { b2 = d; i2 = k; }
        }
    }

    // weights exactly as reference: 1/(sqrt(max(d2,1e-12))+1e-8), normalized
    float w0 = 1.f / (sqrtf(fmaxf(b0, 1e-12f)) + 1e-8f);
    float w1 = 1.f / (sqrtf(fmaxf(b1, 1e-12f)) + 1e-8f);
    float w2 = 1.f / (sqrtf(fmaxf(b2, 1e-12f)) + 1e-8f);
    float ws = w0 + w1 + w2;
    w0 = w0 / ws; w1 = w1 / ws; w2 = w2 / ws;

    // warp-cooperative gather: lane s's query served by the whole warp
    const unsigned full = 0xffffffffu;
    const int warp = tid >> 5, lane = tid & 31;
    const int h2base = scene * N2_PER;
    const int qbase  = scene * N1_PER + blockIdx.x * 256 + warp * 32;

    for (int s = 0; s < 32; s++) {
        float ww0 = __shfl_sync(full, w0, s);
        float ww1 = __shfl_sync(full, w1, s);
        float ww2 = __shfl_sync(full, w2, s);
        int   j0  = __shfl_sync(full, i0, s);
        int   j1  = __shfl_sync(full, i1, s);
        int   j2  = __shfl_sync(full, i2, s);
        const float4* r0 = (const float4*)(g_h2 + (size_t)(h2base + j0) * 256);
        const float4* r1 = (const float4*)(g_h2 + (size_t)(h2base + j1) * 256);
        const float4* r2 = (const float4*)(g_h2 + (size_t)(h2base + j2) * 256);
        float4* o = (float4*)(out + (size_t)(qbase + s) * 256);
#pragma unroll
        for (int c = 0; c < 2; c++) {
            int ci = lane + c * 32;         // 0..63 float4 slots (256 floats)
            float4 a = r0[ci], b = r1[ci], cc = r2[ci], ov = o[ci];
            ov.x += ww0 * a.x + ww1 * b.x + ww2 * cc.x;
            ov.y += ww0 * a.y + ww1 * b.y + ww2 * cc.y;
            ov.z += ww0 * a.z + ww1 * b.z + ww2 * cc.z;
            ov.w += ww0 * a.w + ww1 * b.w + ww2 * cc.w;
            o[ci] = ov;
        }
    }
}

// ---------------- launch -----------------
extern "C" void kernel_launch(void* const* d_in, const int* in_sizes, int n_in,
                              void* d_out, int out_size)
{
    const float* p1  = (const float*)d_in[0];
    const float* x1  = (const float*)d_in[1];
    const float* p2  = (const float*)d_in[2];
    const float* x2  = (const float*)d_in[3];
    const float* W1  = (const float*)d_in[4];
    const float* b1  = (const float*)d_in[5];
    const float* g1  = (const float*)d_in[6];
    const float* be1 = (const float*)d_in[7];
    const float* m1  = (const float*)d_in[8];
    const float* v1  = (const float*)d_in[9];
    const float* W2  = (const float*)d_in[10];
    const float* b2  = (const float*)d_in[11];
    const float* g2  = (const float*)d_in[12];
    const float* be2 = (const float*)d_in[13];
    const float* m2  = (const float*)d_in[14];
    const float* v2  = (const float*)d_in[15];
    float* out = (float*)d_out;

    // fold BN into weights/bias
    fold_kernel<0><<<C_OUT, 128>>>(W1, b1, g1, be1, m1, v1);
    fold_kernel<1><<<C_OUT, 128>>>(W2, b2, g2, be2, m2, v2);

    // h1 = relu(bn(x1@W1^T)) -> out directly
    {
        float* h2_dev = nullptr;  // gemm<1> writes to g_h2 internally via pointer arg
        (void)h2_dev;
        dim3 grid1(2, N1_TOT / 128);
        gemm_bias_relu<0><<<grid1, 256>>>(x1, out, N1_TOT, C_OUT);
    }
    // h2 = relu(bn(x2@W2^T)) -> g_h2
    {
        float* h2ptr = nullptr;
        cudaGetSymbolAddress((void**)&h2ptr, g_h2);
        dim3 grid2(2, N2_TOT / 128);
        gemm_bias_relu<1><<<grid2, 256>>>(x2, h2ptr, N2_TOT, C_IN);
    }

    // kNN interpolation, accumulate into out
    static bool attr_set = false;
    if (!attr_set) {
        cudaFuncSetAttribute(knn_interp_kernel,
                             cudaFuncAttributeMaxDynamicSharedMemorySize,
                             N2_PER * sizeof(float4));
        attr_set = true;
    }
    dim3 gridk(N1_PER / 256, BATCH);
    knn_interp_kernel<<<gridk, 256, N2_PER * sizeof(float4)>>>(p1, p2, out);
}